// round 15
// baseline (speedup 1.0000x reference)
#include <cuda_runtime.h>
#include <cuda_fp16.h>

#define NN 100000
#define NE 1600000
#define NS 3
#define DIN 128
#define DOUT 64
#define ROW (NS*DOUT)    /* 192 halfs per node state row */
#define HROW 96          /* 96 half2 per node row */
#define DEPTH 10

// ---------------- device scratch (static: no allocation allowed) ----------------
__device__ __half2 g_hA  [NN*HROW];    // fp16 state (double buffered)
__device__ __half2 g_hB  [NN*HROW];
__device__ __half2 g_temb[NN*HROW];    // fp16 t*emb (teleport term)
__device__ float   g_satt[NN*DOUT];    // fp32 s_att = data@W_src + b_src
__device__ float   g_wt  [DOUT*DOUT];  // W_tgt transposed
__device__ int     g_cnt[NN];
__device__ int     g_rowptr[NN+1];
__device__ int     g_cursor[NN];
__device__ float   g_deginv[NN];
__device__ int     g_col[NE];
__device__ int     g_scan[NN];
__device__ int     g_bsum[128];
__device__ int     g_boff[128];
__device__ int     g_done;

// f32x2 helpers (FFMA2 only reachable via PTX)
__device__ __forceinline__ unsigned long long fma2(unsigned long long a,
                                                   unsigned long long b,
                                                   unsigned long long c) {
    unsigned long long r;
    asm("fma.rn.f32x2 %0, %1, %2, %3;" : "=l"(r) : "l"(a), "l"(b), "l"(c));
    return r;
}
__device__ __forceinline__ unsigned long long bcast2(float x) {
    unsigned long long r;
    asm("mov.b64 %0, {%1, %1};" : "=l"(r) : "f"(x));
    return r;
}
__device__ __forceinline__ float2 unpk2(unsigned long long a) {
    float2 v;
    asm("mov.b64 {%0, %1}, %2;" : "=f"(v.x), "=f"(v.y) : "l"(a));
    return v;
}

// ---------------- launch 0: histogram ----------------
__global__ void k_hist(const int* __restrict__ tgt) {
    int e = blockIdx.x*blockDim.x + threadIdx.x;
    if (e < NE) atomicAdd(&g_cnt[tgt[e]], 1);
}

// ---------------- launch 1: fused scan (decoupled last-block finish) ----------
__global__ void k_scan() {
    __shared__ int sh[1024];
    __shared__ bool s_last;
    int t = threadIdx.x;
    int i = blockIdx.x*1024 + t;
    int v = (i < NN) ? g_cnt[i] : 0;
    sh[t] = v;
    __syncthreads();
    for (int off = 1; off < 1024; off <<= 1) {
        int add = (t >= off) ? sh[t-off] : 0;
        __syncthreads();
        sh[t] += add;
        __syncthreads();
    }
    if (i < NN) g_scan[i] = sh[t];
    if (t == 1023) g_bsum[blockIdx.x] = sh[1023];
    __threadfence();
    if (t == 0) {
        int done = atomicAdd(&g_done, 1);
        s_last = (done == (int)gridDim.x - 1);
    }
    __syncthreads();
    if (!s_last) return;
    __threadfence();
    if (t == 0) {
        int run = 0;
        for (int b = 0; b < (int)gridDim.x; b++) { g_boff[b] = run; run += g_bsum[b]; }
        g_done = 0;
        g_rowptr[NN] = NE;
    }
    __syncthreads();
    for (int k = t; k < NN; k += 1024) {
        int cnt  = g_cnt[k];
        int excl = g_scan[k] - cnt + g_boff[k >> 10];
        g_rowptr[k] = excl;
        g_cursor[k] = excl;
        g_deginv[k] = 1.0f / (float)max(cnt, 1);
    }
}

// ---------------- launch 2: CSR fill (+re-zero g_cnt) + W_tgt transpose --------
__global__ void __launch_bounds__(256) k_fill(const int* __restrict__ src,
                                              const int* __restrict__ tgt,
                                              const float* __restrict__ W_tgt) {
    int bid = blockIdx.x;
    int tid = threadIdx.x;
    if (bid == 6250) {
        for (int i = tid; i < DOUT*DOUT; i += 256) {
            int p = i >> 6, o = i & 63;
            g_wt[o*DOUT + p] = W_tgt[i];
        }
        return;
    }
    int e = bid*256 + tid;
    if (e < NE) {
        int p = atomicAdd(&g_cursor[tgt[e]], 1);
        g_col[p] = src[e];
    }
    if (e < NN) g_cnt[e] = 0;
}

// ---------------- launch 3: tiled GEMM — 3 emb slices + s_att slice -------------
// Block = 64 nodes x 64 outs with 128 threads; thread = 8 nodes x 4 outs.
// LDS amplification 1/8 + 1/4 = 0.375 (vs 0.5 for 4x4): ~20% fewer wavefronts.
__global__ void __launch_bounds__(128) k_emb(const float* __restrict__ data,
                                             const float* __restrict__ Ws,
                                             const float* __restrict__ bs,
                                             const float* __restrict__ W_src,
                                             const float* __restrict__ b_src) {
    __shared__ float sw[DIN*DOUT];    // 32KB: sw[k][o]
    __shared__ float sd[64*64];       // 16KB: half-k tile, chunk-XOR swizzled
    int tid = threadIdx.x;
    int s   = blockIdx.y;             // 0..3
    int n0  = blockIdx.x * 64;

    const float* Wp = (s < NS) ? (Ws + (size_t)s*DIN*DOUT) : W_src;
    const float* bp = (s < NS) ? (bs + s*DOUT)             : b_src;

    {
        const float4* Wg = (const float4*)Wp;
        float4* sw4 = (float4*)sw;
        #pragma unroll
        for (int i = tid; i < DIN*DOUT/4; i += 128) sw4[i] = __ldg(&Wg[i]);
    }

    int nd8 = tid >> 4;               // node octet (0..7): nodes nd8*8..+7
    int oq  = tid & 15;               // out quad (0..15): outs oq*4..+3
    const unsigned long long* bsp = (const unsigned long long*)(bp + oq*4);
    unsigned long long acc[8][2];
    {
        unsigned long long b01 = bsp[0], b23 = bsp[1];
        #pragma unroll
        for (int i = 0; i < 8; i++) { acc[i][0] = b01; acc[i][1] = b23; }
    }

    const float4* data4 = (const float4*)data;
    #pragma unroll
    for (int half = 0; half < 2; half++) {
        __syncthreads();
        #pragma unroll
        for (int it = 0; it < 8; it++) {
            int i = it*128 + tid;
            int r = i >> 4, c = i & 15;
            int n = n0 + r;
            float4 v = (n < NN) ? __ldg(&data4[(size_t)n*32 + half*16 + c])
                                : make_float4(0.f, 0.f, 0.f, 0.f);
            *(float4*)&sd[r*64 + ((c ^ (r & 7)) << 2)] = v;
        }
        __syncthreads();

        #pragma unroll 4
        for (int k4 = 0; k4 < 16; k4++) {
            float4 dv[8];
            #pragma unroll
            for (int i = 0; i < 8; i++) {
                int r = nd8*8 + i;
                dv[i] = *(const float4*)&sd[r*64 + ((k4 ^ (r & 7)) << 2)];
            }
            #pragma unroll
            for (int j = 0; j < 4; j++) {
                int k = half*64 + k4*4 + j;
                ulonglong2 w = *(const ulonglong2*)&sw[k*DOUT + (oq << 2)];
                #pragma unroll
                for (int i = 0; i < 8; i++) {
                    unsigned long long db = bcast2(((const float*)&dv[i])[j]);
                    acc[i][0] = fma2(db, w.x, acc[i][0]);
                    acc[i][1] = fma2(db, w.y, acc[i][1]);
                }
            }
        }
    }

    if (s < NS) {
        const float tv[NS] = {0.1f, 0.2f, 0.3f};
        float t = tv[s];
        #pragma unroll
        for (int i = 0; i < 8; i++) {
            int n = n0 + nd8*8 + i;
            if (n >= NN) continue;
            float2 f0 = unpk2(acc[i][0]), f1 = unpk2(acc[i][1]);
            size_t idx2 = ((size_t)n*ROW + s*DOUT + oq*4) >> 1;
            g_hA[idx2]     = __float22half2_rn(f0);
            g_hA[idx2 + 1] = __float22half2_rn(f1);
            g_temb[idx2]     = __floats2half2_rn(t*f0.x, t*f0.y);
            g_temb[idx2 + 1] = __floats2half2_rn(t*f1.x, t*f1.y);
        }
    } else {
        #pragma unroll
        for (int i = 0; i < 8; i++) {
            int n = n0 + nd8*8 + i;
            if (n >= NN) continue;
            float2 f0 = unpk2(acc[i][0]), f1 = unpk2(acc[i][1]);
            *(float4*)&g_satt[(size_t)n*DOUT + oq*4] =
                make_float4(f0.x, f0.y, f1.x, f1.y);
        }
    }
}

// -------- shared gather body (lane owns half2 col `lane` per scale group) --------
// fp16 tree reduction: octets (depth-3 HADD2) -> quads -> singles; fp32 across.
__device__ __forceinline__ void gather_sums(const __half2* __restrict__ xh,
                                            int beg, int end, int lane,
                                            float* a) {
    int j = beg;
    for (; j < end && (j & 3); j++) {
        int c = __ldg(&g_col[j]);
        const __half2* r = xh + (size_t)c*HROW;
        float2 v0 = __half22float2(r[lane]);
        float2 v1 = __half22float2(r[32+lane]);
        float2 v2 = __half22float2(r[64+lane]);
        a[0] += v0.x; a[1] += v0.y;
        a[2] += v1.x; a[3] += v1.y;
        a[4] += v2.x; a[5] += v2.y;
    }
    for (; j + 8 <= end; j += 8) {
        int4 ca = __ldg((const int4*)&g_col[j]);
        int4 cb = __ldg((const int4*)&g_col[j+4]);
        const __half2* r0 = xh + (size_t)ca.x*HROW;
        const __half2* r1 = xh + (size_t)ca.y*HROW;
        const __half2* r2 = xh + (size_t)ca.z*HROW;
        const __half2* r3 = xh + (size_t)ca.w*HROW;
        const __half2* r4 = xh + (size_t)cb.x*HROW;
        const __half2* r5 = xh + (size_t)cb.y*HROW;
        const __half2* r6 = xh + (size_t)cb.z*HROW;
        const __half2* r7 = xh + (size_t)cb.w*HROW;
        #pragma unroll
        for (int g = 0; g < 3; g++) {
            int off = g*32 + lane;
            __half2 t0 = __hadd2(r0[off], r1[off]);
            __half2 t1 = __hadd2(r2[off], r3[off]);
            __half2 t2 = __hadd2(r4[off], r5[off]);
            __half2 t3 = __hadd2(r6[off], r7[off]);
            __half2 sfull = __hadd2(__hadd2(t0, t1), __hadd2(t2, t3));
            float2 f = __half22float2(sfull);
            a[2*g]   += f.x;
            a[2*g+1] += f.y;
        }
    }
    if (j + 4 <= end) {
        int4 c = __ldg((const int4*)&g_col[j]);
        const __half2* r0 = xh + (size_t)c.x*HROW;
        const __half2* r1 = xh + (size_t)c.y*HROW;
        const __half2* r2 = xh + (size_t)c.z*HROW;
        const __half2* r3 = xh + (size_t)c.w*HROW;
        #pragma unroll
        for (int g = 0; g < 3; g++) {
            int off = g*32 + lane;
            __half2 sfull = __hadd2(__hadd2(r0[off], r1[off]),
                                    __hadd2(r2[off], r3[off]));
            float2 f = __half22float2(sfull);
            a[2*g]   += f.x;
            a[2*g+1] += f.y;
        }
        j += 4;
    }
    for (; j < end; j++) {
        int c = __ldg(&g_col[j]);
        const __half2* r = xh + (size_t)c*HROW;
        float2 v0 = __half22float2(r[lane]);
        float2 v1 = __half22float2(r[32+lane]);
        float2 v2 = __half22float2(r[64+lane]);
        a[0] += v0.x; a[1] += v0.y;
        a[2] += v1.x; a[3] += v1.y;
        a[4] += v2.x; a[5] += v2.y;
    }
}

// ---------------- launches 4..12: propagation steps 1..9 -------------------------
__global__ void __launch_bounds__(256) k_prop(const __half2* __restrict__ xh,
                                              __half2* __restrict__ yh) {
    int w    = (blockIdx.x*blockDim.x + threadIdx.x) >> 5;
    int lane = threadIdx.x & 31;
    int beg = g_rowptr[w], end = g_rowptr[w+1];

    float a[6] = {0.f,0.f,0.f,0.f,0.f,0.f};
    gather_sums(xh, beg, end, lane, a);

    const __half2* tm = g_temb + (size_t)w*HROW;
    __half2* hr = yh + (size_t)w*HROW;

    if (end > beg) {
        const __half2* xo = xh + (size_t)w*HROW;
        float dinv = g_deginv[w];
        const float i0 = 0.9f, i1 = 0.8f, i2 = 0.7f;
        float2 e0 = __half22float2(tm[lane]);
        float2 e1 = __half22float2(tm[32 + lane]);
        float2 e2 = __half22float2(tm[64 + lane]);
        float2 o0 = __half22float2(xo[lane]);
        float2 o1 = __half22float2(xo[32 + lane]);
        float2 o2 = __half22float2(xo[64 + lane]);
        float2 r;
        r.x = i0*(o0.x - a[0]*dinv) + e0.x;
        r.y = i0*(o0.y - a[1]*dinv) + e0.y;  hr[lane]      = __float22half2_rn(r);
        r.x = i1*(o1.x - a[2]*dinv) + e1.x;
        r.y = i1*(o1.y - a[3]*dinv) + e1.y;  hr[32 + lane] = __float22half2_rn(r);
        r.x = i2*(o2.x - a[4]*dinv) + e2.x;
        r.y = i2*(o2.y - a[5]*dinv) + e2.y;  hr[64 + lane] = __float22half2_rn(r);
    } else {
        hr[lane]      = tm[lane];
        hr[32 + lane] = tm[32 + lane];
        hr[64 + lane] = tm[64 + lane];
    }
}

// ---------------- launch 13: prop step 10 FUSED with attention epilogue ----------
__global__ void __launch_bounds__(256) k_prop_final(
        const __half2* __restrict__ xh,
        const float* __restrict__ b_tgt, float* __restrict__ out) {
    __shared__ float ssf[8][DOUT];
    int tid  = threadIdx.x;
    int wid  = tid >> 5;
    int lane = tid & 31;
    int w = blockIdx.x*8 + wid;
    int beg = g_rowptr[w], end = g_rowptr[w+1];

    float a[6] = {0.f,0.f,0.f,0.f,0.f,0.f};
    gather_sums(xh, beg, end, lane, a);

    const __half2* tm = g_temb + (size_t)w*HROW;
    float sc[NS][2];
    if (end > beg) {
        const __half2* xo = xh + (size_t)w*HROW;
        float dinv = g_deginv[w];
        const float it[NS] = {0.9f, 0.8f, 0.7f};
        #pragma unroll
        for (int s = 0; s < NS; s++) {
            float2 e = __half22float2(tm[s*32 + lane]);
            float2 o = __half22float2(xo[s*32 + lane]);
            sc[s][0] = fmaxf(it[s]*(o.x - a[2*s]*dinv)   + e.x, 0.f);
            sc[s][1] = fmaxf(it[s]*(o.y - a[2*s+1]*dinv) + e.y, 0.f);
        }
    } else {
        #pragma unroll
        for (int s = 0; s < NS; s++) {
            float2 e = __half22float2(tm[s*32 + lane]);
            sc[s][0] = fmaxf(e.x, 0.f);
            sc[s][1] = fmaxf(e.y, 0.f);
        }
    }

    float2 sa = ((const float2*)g_satt)[(size_t)w*32 + lane];
    ssf[wid][2*lane]     = sa.x;
    ssf[wid][2*lane + 1] = sa.y;
    __syncwarp();

    const float2* wt2 = (const float2*)g_wt;
    float u0 = 0.f, u1 = 0.f;
    #pragma unroll 8
    for (int o = 0; o < DOUT; o++) {
        float s = ssf[wid][o];
        float2 wv = __ldg(&wt2[o*32 + lane]);
        u0 += wv.x * s;
        u1 += wv.y * s;
    }

    float2 btv = ((const float2*)b_tgt)[lane];
    float cp = btv.x*sa.x + btv.y*sa.y;
    for (int m = 16; m; m >>= 1) cp += __shfl_xor_sync(0xffffffffu, cp, m);

    float lg[NS];
    #pragma unroll
    for (int s = 0; s < NS; s++) {
        float p = sc[s][0]*u0 + sc[s][1]*u1;
        for (int m = 16; m; m >>= 1) p += __shfl_xor_sync(0xffffffffu, p, m);
        lg[s] = p + cp;
    }

    float mx = fmaxf(lg[0], fmaxf(lg[1], lg[2]));
    float e0 = expf(lg[0]-mx), e1 = expf(lg[1]-mx), e2 = expf(lg[2]-mx);
    float inv = 1.f / (e0 + e1 + e2);
    float w0 = e0*inv, w1 = e1*inv, w2 = e2*inv;

    float2 ov;
    ov.x = w0*sc[0][0] + w1*sc[1][0] + w2*sc[2][0];
    ov.y = w0*sc[0][1] + w1*sc[1][1] + w2*sc[2][1];
    ((float2*)out)[(size_t)w*32 + lane] = ov;
}

// ---------------- launch ----------------
extern "C" void kernel_launch(void* const* d_in, const int* in_sizes, int n_in,
                              void* d_out, int out_size) {
    const float* data  = (const float*)d_in[0];
    const int*   src   = (const int*)  d_in[1];
    const int*   tgt   = (const int*)  d_in[2];
    const float* Ws    = (const float*)d_in[3];
    const float* bs    = (const float*)d_in[4];
    const float* W_src = (const float*)d_in[5];
    const float* b_src = (const float*)d_in[6];
    const float* W_tgt = (const float*)d_in[7];
    const float* b_tgt = (const float*)d_in[8];
    float* out = (float*)d_out;

    k_hist<<<(NE+255)/256, 256>>>(tgt);            // launch 0
    k_scan<<<(NN+1023)/1024, 1024>>>();            // launch 1
    k_fill<<<6251, 256>>>(src, tgt, W_tgt);        // launch 2
    dim3 ge((NN + 63)/64, NS + 1);
    k_emb<<<ge, 128>>>(data, Ws, bs, W_src, b_src);  // launch 3 (profiled)

    __half2 *hA, *hB;
    cudaGetSymbolAddress((void**)&hA, g_hA);
    cudaGetSymbolAddress((void**)&hB, g_hB);

    const __half2* cur = hA;
    __half2*       nxt = hB;
    for (int d = 0; d < DEPTH - 1; d++) {          // launches 4..12 (9 steps)
        k_prop<<<NN/8, 256>>>(cur, nxt);
        const __half2* tmp = nxt;
        nxt = (__half2*)cur;
        cur = tmp;
    }

    // launch 13: step 10 fused with attention epilogue
    k_prop_final<<<NN/8, 256>>>(cur, b_tgt, out);
}

// round 16
// speedup vs baseline: 1.0369x; 1.0369x over previous
#include <cuda_runtime.h>
#include <cuda_fp16.h>

#define NN 100000
#define NE 1600000
#define NS 3
#define DIN 128
#define DOUT 64
#define ROW (NS*DOUT)    /* 192 halfs per node state row */
#define HROW 96          /* 96 half2 per node row */
#define DEPTH 10

// ---------------- device scratch (static: no allocation allowed) ----------------
__device__ __half2 g_hA  [NN*HROW];    // fp16 state (double buffered)
__device__ __half2 g_hB  [NN*HROW];
__device__ __half2 g_temb[NN*HROW];    // fp16 t*emb (teleport term)
__device__ float   g_satt[NN*DOUT];    // fp32 s_att = data@W_src + b_src
__device__ float   g_wt  [DOUT*DOUT];  // W_tgt transposed
__device__ int     g_cnt[NN];
__device__ int     g_rowptr[NN+1];
__device__ int     g_cursor[NN];
__device__ float   g_deginv[NN];
__device__ int     g_col[NE];
__device__ int     g_scan[NN];
__device__ int     g_bsum[128];
__device__ int     g_boff[128];
__device__ int     g_done;

// f32x2 helpers (FFMA2 only reachable via PTX)
__device__ __forceinline__ unsigned long long fma2(unsigned long long a,
                                                   unsigned long long b,
                                                   unsigned long long c) {
    unsigned long long r;
    asm("fma.rn.f32x2 %0, %1, %2, %3;" : "=l"(r) : "l"(a), "l"(b), "l"(c));
    return r;
}
__device__ __forceinline__ unsigned long long bcast2(float x) {
    unsigned long long r;
    asm("mov.b64 %0, {%1, %1};" : "=l"(r) : "f"(x));
    return r;
}
__device__ __forceinline__ float2 unpk2(unsigned long long a) {
    float2 v;
    asm("mov.b64 {%0, %1}, %2;" : "=f"(v.x), "=f"(v.y) : "l"(a));
    return v;
}

// ---------------- launch 0: histogram ----------------
__global__ void k_hist(const int* __restrict__ tgt) {
    int e = blockIdx.x*blockDim.x + threadIdx.x;
    if (e < NE) atomicAdd(&g_cnt[tgt[e]], 1);
}

// ---------------- launch 1: fused scan (decoupled last-block finish) ----------
__global__ void k_scan() {
    __shared__ int sh[1024];
    __shared__ bool s_last;
    int t = threadIdx.x;
    int i = blockIdx.x*1024 + t;
    int v = (i < NN) ? g_cnt[i] : 0;
    sh[t] = v;
    __syncthreads();
    for (int off = 1; off < 1024; off <<= 1) {
        int add = (t >= off) ? sh[t-off] : 0;
        __syncthreads();
        sh[t] += add;
        __syncthreads();
    }
    if (i < NN) g_scan[i] = sh[t];
    if (t == 1023) g_bsum[blockIdx.x] = sh[1023];
    __threadfence();
    if (t == 0) {
        int done = atomicAdd(&g_done, 1);
        s_last = (done == (int)gridDim.x - 1);
    }
    __syncthreads();
    if (!s_last) return;
    __threadfence();
    if (t == 0) {
        int run = 0;
        for (int b = 0; b < (int)gridDim.x; b++) { g_boff[b] = run; run += g_bsum[b]; }
        g_done = 0;
        g_rowptr[NN] = NE;
    }
    __syncthreads();
    for (int k = t; k < NN; k += 1024) {
        int cnt  = g_cnt[k];
        int excl = g_scan[k] - cnt + g_boff[k >> 10];
        g_rowptr[k] = excl;
        g_cursor[k] = excl;
        g_deginv[k] = 1.0f / (float)max(cnt, 1);
    }
}

// ---------------- launch 2: CSR fill (+re-zero g_cnt) + W_tgt transpose --------
__global__ void __launch_bounds__(256) k_fill(const int* __restrict__ src,
                                              const int* __restrict__ tgt,
                                              const float* __restrict__ W_tgt) {
    int bid = blockIdx.x;
    int tid = threadIdx.x;
    if (bid == 6250) {
        for (int i = tid; i < DOUT*DOUT; i += 256) {
            int p = i >> 6, o = i & 63;
            g_wt[o*DOUT + p] = W_tgt[i];
        }
        return;
    }
    int e = bid*256 + tid;
    if (e < NE) {
        int p = atomicAdd(&g_cursor[tgt[e]], 1);
        g_col[p] = src[e];
    }
    if (e < NN) g_cnt[e] = 0;
}

// ---------------- launch 3: tiled GEMM — 3 emb slices + s_att slice -------------
// Block = 64 nodes x 64 outs with 128 threads; thread = 8 nodes x 4 outs.
// (R15 version, measured 142us.)
__global__ void __launch_bounds__(128) k_emb(const float* __restrict__ data,
                                             const float* __restrict__ Ws,
                                             const float* __restrict__ bs,
                                             const float* __restrict__ W_src,
                                             const float* __restrict__ b_src) {
    __shared__ float sw[DIN*DOUT];    // 32KB: sw[k][o]
    __shared__ float sd[64*64];       // 16KB: half-k tile, chunk-XOR swizzled
    int tid = threadIdx.x;
    int s   = blockIdx.y;             // 0..3
    int n0  = blockIdx.x * 64;

    const float* Wp = (s < NS) ? (Ws + (size_t)s*DIN*DOUT) : W_src;
    const float* bp = (s < NS) ? (bs + s*DOUT)             : b_src;

    {
        const float4* Wg = (const float4*)Wp;
        float4* sw4 = (float4*)sw;
        #pragma unroll
        for (int i = tid; i < DIN*DOUT/4; i += 128) sw4[i] = __ldg(&Wg[i]);
    }

    int nd8 = tid >> 4;               // node octet (0..7): nodes nd8*8..+7
    int oq  = tid & 15;               // out quad (0..15): outs oq*4..+3
    const unsigned long long* bsp = (const unsigned long long*)(bp + oq*4);
    unsigned long long acc[8][2];
    {
        unsigned long long b01 = bsp[0], b23 = bsp[1];
        #pragma unroll
        for (int i = 0; i < 8; i++) { acc[i][0] = b01; acc[i][1] = b23; }
    }

    const float4* data4 = (const float4*)data;
    #pragma unroll
    for (int half = 0; half < 2; half++) {
        __syncthreads();
        #pragma unroll
        for (int it = 0; it < 8; it++) {
            int i = it*128 + tid;
            int r = i >> 4, c = i & 15;
            int n = n0 + r;
            float4 v = (n < NN) ? __ldg(&data4[(size_t)n*32 + half*16 + c])
                                : make_float4(0.f, 0.f, 0.f, 0.f);
            *(float4*)&sd[r*64 + ((c ^ (r & 7)) << 2)] = v;
        }
        __syncthreads();

        #pragma unroll 4
        for (int k4 = 0; k4 < 16; k4++) {
            float4 dv[8];
            #pragma unroll
            for (int i = 0; i < 8; i++) {
                int r = nd8*8 + i;
                dv[i] = *(const float4*)&sd[r*64 + ((k4 ^ (r & 7)) << 2)];
            }
            #pragma unroll
            for (int j = 0; j < 4; j++) {
                int k = half*64 + k4*4 + j;
                ulonglong2 w = *(const ulonglong2*)&sw[k*DOUT + (oq << 2)];
                #pragma unroll
                for (int i = 0; i < 8; i++) {
                    unsigned long long db = bcast2(((const float*)&dv[i])[j]);
                    acc[i][0] = fma2(db, w.x, acc[i][0]);
                    acc[i][1] = fma2(db, w.y, acc[i][1]);
                }
            }
        }
    }

    if (s < NS) {
        const float tv[NS] = {0.1f, 0.2f, 0.3f};
        float t = tv[s];
        #pragma unroll
        for (int i = 0; i < 8; i++) {
            int n = n0 + nd8*8 + i;
            if (n >= NN) continue;
            float2 f0 = unpk2(acc[i][0]), f1 = unpk2(acc[i][1]);
            size_t idx2 = ((size_t)n*ROW + s*DOUT + oq*4) >> 1;
            g_hA[idx2]     = __float22half2_rn(f0);
            g_hA[idx2 + 1] = __float22half2_rn(f1);
            g_temb[idx2]     = __floats2half2_rn(t*f0.x, t*f0.y);
            g_temb[idx2 + 1] = __floats2half2_rn(t*f1.x, t*f1.y);
        }
    } else {
        #pragma unroll
        for (int i = 0; i < 8; i++) {
            int n = n0 + nd8*8 + i;
            if (n >= NN) continue;
            float2 f0 = unpk2(acc[i][0]), f1 = unpk2(acc[i][1]);
            *(float4*)&g_satt[(size_t)n*DOUT + oq*4] =
                make_float4(f0.x, f0.y, f1.x, f1.y);
        }
    }
}

// -------- shared gather body (R12/R14 QUAD version — measured 57us/step) ---------
__device__ __forceinline__ void gather_sums(const __half2* __restrict__ xh,
                                            int beg, int end, int lane,
                                            float* a) {
    int j = beg;
    for (; j < end && (j & 3); j++) {
        int c = __ldg(&g_col[j]);
        const __half2* r = xh + (size_t)c*HROW;
        float2 v0 = __half22float2(r[lane]);
        float2 v1 = __half22float2(r[32+lane]);
        float2 v2 = __half22float2(r[64+lane]);
        a[0] += v0.x; a[1] += v0.y;
        a[2] += v1.x; a[3] += v1.y;
        a[4] += v2.x; a[5] += v2.y;
    }
    for (; j + 4 <= end; j += 4) {
        int4 c = __ldg((const int4*)&g_col[j]);
        const __half2* r0 = xh + (size_t)c.x*HROW;
        const __half2* r1 = xh + (size_t)c.y*HROW;
        const __half2* r2 = xh + (size_t)c.z*HROW;
        const __half2* r3 = xh + (size_t)c.w*HROW;
        __half2 s01 = __hadd2(r0[lane],    r1[lane]);
        __half2 s23 = __hadd2(r2[lane],    r3[lane]);
        float2 f01 = __half22float2(s01), f23 = __half22float2(s23);
        a[0] += f01.x + f23.x; a[1] += f01.y + f23.y;
        s01 = __hadd2(r0[32+lane], r1[32+lane]);
        s23 = __hadd2(r2[32+lane], r3[32+lane]);
        f01 = __half22float2(s01); f23 = __half22float2(s23);
        a[2] += f01.x + f23.x; a[3] += f01.y + f23.y;
        s01 = __hadd2(r0[64+lane], r1[64+lane]);
        s23 = __hadd2(r2[64+lane], r3[64+lane]);
        f01 = __half22float2(s01); f23 = __half22float2(s23);
        a[4] += f01.x + f23.x; a[5] += f01.y + f23.y;
    }
    for (; j < end; j++) {
        int c = __ldg(&g_col[j]);
        const __half2* r = xh + (size_t)c*HROW;
        float2 v0 = __half22float2(r[lane]);
        float2 v1 = __half22float2(r[32+lane]);
        float2 v2 = __half22float2(r[64+lane]);
        a[0] += v0.x; a[1] += v0.y;
        a[2] += v1.x; a[3] += v1.y;
        a[4] += v2.x; a[5] += v2.y;
    }
}

// ---------------- launches 4..12: propagation steps 1..9 -------------------------
__global__ void __launch_bounds__(256) k_prop(const __half2* __restrict__ xh,
                                              __half2* __restrict__ yh) {
    int w    = (blockIdx.x*blockDim.x + threadIdx.x) >> 5;
    int lane = threadIdx.x & 31;
    int beg = g_rowptr[w], end = g_rowptr[w+1];

    float a[6] = {0.f,0.f,0.f,0.f,0.f,0.f};
    gather_sums(xh, beg, end, lane, a);

    const __half2* tm = g_temb + (size_t)w*HROW;
    __half2* hr = yh + (size_t)w*HROW;

    if (end > beg) {
        const __half2* xo = xh + (size_t)w*HROW;
        float dinv = g_deginv[w];
        const float i0 = 0.9f, i1 = 0.8f, i2 = 0.7f;
        float2 e0 = __half22float2(tm[lane]);
        float2 e1 = __half22float2(tm[32 + lane]);
        float2 e2 = __half22float2(tm[64 + lane]);
        float2 o0 = __half22float2(xo[lane]);
        float2 o1 = __half22float2(xo[32 + lane]);
        float2 o2 = __half22float2(xo[64 + lane]);
        float2 r;
        r.x = i0*(o0.x - a[0]*dinv) + e0.x;
        r.y = i0*(o0.y - a[1]*dinv) + e0.y;  hr[lane]      = __float22half2_rn(r);
        r.x = i1*(o1.x - a[2]*dinv) + e1.x;
        r.y = i1*(o1.y - a[3]*dinv) + e1.y;  hr[32 + lane] = __float22half2_rn(r);
        r.x = i2*(o2.x - a[4]*dinv) + e2.x;
        r.y = i2*(o2.y - a[5]*dinv) + e2.y;  hr[64 + lane] = __float22half2_rn(r);
    } else {
        hr[lane]      = tm[lane];
        hr[32 + lane] = tm[32 + lane];
        hr[64 + lane] = tm[64 + lane];
    }
}

// ---------------- launch 13: prop step 10 FUSED with attention epilogue ----------
__global__ void __launch_bounds__(256) k_prop_final(
        const __half2* __restrict__ xh,
        const float* __restrict__ b_tgt, float* __restrict__ out) {
    __shared__ float ssf[8][DOUT];
    int tid  = threadIdx.x;
    int wid  = tid >> 5;
    int lane = tid & 31;
    int w = blockIdx.x*8 + wid;
    int beg = g_rowptr[w], end = g_rowptr[w+1];

    float a[6] = {0.f,0.f,0.f,0.f,0.f,0.f};
    gather_sums(xh, beg, end, lane, a);

    const __half2* tm = g_temb + (size_t)w*HROW;
    float sc[NS][2];
    if (end > beg) {
        const __half2* xo = xh + (size_t)w*HROW;
        float dinv = g_deginv[w];
        const float it[NS] = {0.9f, 0.8f, 0.7f};
        #pragma unroll
        for (int s = 0; s < NS; s++) {
            float2 e = __half22float2(tm[s*32 + lane]);
            float2 o = __half22float2(xo[s*32 + lane]);
            sc[s][0] = fmaxf(it[s]*(o.x - a[2*s]*dinv)   + e.x, 0.f);
            sc[s][1] = fmaxf(it[s]*(o.y - a[2*s+1]*dinv) + e.y, 0.f);
        }
    } else {
        #pragma unroll
        for (int s = 0; s < NS; s++) {
            float2 e = __half22float2(tm[s*32 + lane]);
            sc[s][0] = fmaxf(e.x, 0.f);
            sc[s][1] = fmaxf(e.y, 0.f);
        }
    }

    float2 sa = ((const float2*)g_satt)[(size_t)w*32 + lane];
    ssf[wid][2*lane]     = sa.x;
    ssf[wid][2*lane + 1] = sa.y;
    __syncwarp();

    const float2* wt2 = (const float2*)g_wt;
    float u0 = 0.f, u1 = 0.f;
    #pragma unroll 8
    for (int o = 0; o < DOUT; o++) {
        float s = ssf[wid][o];
        float2 wv = __ldg(&wt2[o*32 + lane]);
        u0 += wv.x * s;
        u1 += wv.y * s;
    }

    float2 btv = ((const float2*)b_tgt)[lane];
    float cp = btv.x*sa.x + btv.y*sa.y;
    for (int m = 16; m; m >>= 1) cp += __shfl_xor_sync(0xffffffffu, cp, m);

    float lg[NS];
    #pragma unroll
    for (int s = 0; s < NS; s++) {
        float p = sc[s][0]*u0 + sc[s][1]*u1;
        for (int m = 16; m; m >>= 1) p += __shfl_xor_sync(0xffffffffu, p, m);
        lg[s] = p + cp;
    }

    float mx = fmaxf(lg[0], fmaxf(lg[1], lg[2]));
    float e0 = expf(lg[0]-mx), e1 = expf(lg[1]-mx), e2 = expf(lg[2]-mx);
    float inv = 1.f / (e0 + e1 + e2);
    float w0 = e0*inv, w1 = e1*inv, w2 = e2*inv;

    float2 ov;
    ov.x = w0*sc[0][0] + w1*sc[1][0] + w2*sc[2][0];
    ov.y = w0*sc[0][1] + w1*sc[1][1] + w2*sc[2][1];
    ((float2*)out)[(size_t)w*32 + lane] = ov;
}

// ---------------- launch ----------------
extern "C" void kernel_launch(void* const* d_in, const int* in_sizes, int n_in,
                              void* d_out, int out_size) {
    const float* data  = (const float*)d_in[0];
    const int*   src   = (const int*)  d_in[1];
    const int*   tgt   = (const int*)  d_in[2];
    const float* Ws    = (const float*)d_in[3];
    const float* bs    = (const float*)d_in[4];
    const float* W_src = (const float*)d_in[5];
    const float* b_src = (const float*)d_in[6];
    const float* W_tgt = (const float*)d_in[7];
    const float* b_tgt = (const float*)d_in[8];
    float* out = (float*)d_out;

    k_hist<<<(NE+255)/256, 256>>>(tgt);            // launch 0
    k_scan<<<(NN+1023)/1024, 1024>>>();            // launch 1
    k_fill<<<6251, 256>>>(src, tgt, W_tgt);        // launch 2
    dim3 ge((NN + 63)/64, NS + 1);
    k_emb<<<ge, 128>>>(data, Ws, bs, W_src, b_src);  // launch 3 (profiled)

    __half2 *hA, *hB;
    cudaGetSymbolAddress((void**)&hA, g_hA);
    cudaGetSymbolAddress((void**)&hB, g_hB);

    const __half2* cur = hA;
    __half2*       nxt = hB;
    for (int d = 0; d < DEPTH - 1; d++) {          // launches 4..12 (9 steps)
        k_prop<<<NN/8, 256>>>(cur, nxt);
        const __half2* tmp = nxt;
        nxt = (__half2*)cur;
        cur = tmp;
    }

    // launch 13: step 10 fused with attention epilogue
    k_prop_final<<<NN/8, 256>>>(cur, b_tgt, out);
}